// round 6
// baseline (speedup 1.0000x reference)
#include <cuda_runtime.h>
#include <cuda_bf16.h>
#include <cstdint>
#include <math.h>

// ---------------------------------------------------------------------------
// Problem constants
//   B=2, FRAMES=16 -> bf=32 ; TOK=256 ; DIM=1280 ; HEADS=8 ; DH=160
//   CROSS=768 ; ESEQ=77 ; INNER=5120 (geglu), ffn1 N = 10240
// ---------------------------------------------------------------------------
#define BF      32
#define TOK     256
#define DIMC    1280
#define HEADS   8
#define DH      160
#define CROSS   768
#define ESEQ    77
#define FRAMES  16
#define NROWS   (BF*TOK)          // 8192
#define ENCROWS (BF*ESEQ)         // 2464
#define FF_N    (2*4*DIMC)        // 10240
#define FF_I    (4*DIMC)          // 5120

// ---------------------------------------------------------------------------
// Scratch (device globals; no allocation allowed)
// ---------------------------------------------------------------------------
__device__ float g_nh [NROWS*DIMC];
__device__ float g_q  [NROWS*DIMC];
__device__ float g_k  [NROWS*DIMC];
__device__ float g_v  [NROWS*DIMC];
__device__ float g_ao [NROWS*DIMC];
__device__ float g_ht [NROWS*DIMC];
__device__ float g_ff1[(size_t)NROWS*FF_N];
__device__ float g_gg [(size_t)NROWS*FF_I];
__device__ float g_enck[ENCROWS*DIMC];
__device__ float g_encv[ENCROWS*DIMC];

// ---------------------------------------------------------------------------
// LayerNorm: one block (128 threads) per row of 1280
// ---------------------------------------------------------------------------
__global__ __launch_bounds__(128)
void ln_kernel(const float* __restrict__ x, const float* __restrict__ w,
               const float* __restrict__ b, float* __restrict__ y)
{
    int row = blockIdx.x;
    const float* xr = x + (size_t)row * DIMC;
    float*       yr = y + (size_t)row * DIMC;
    int tid = threadIdx.x;

    float v[10];
    float s = 0.f, ss = 0.f;
#pragma unroll
    for (int i = 0; i < 10; i++) {
        float t = xr[tid + i*128];
        v[i] = t; s += t; ss += t*t;
    }
#pragma unroll
    for (int off = 16; off; off >>= 1) {
        s  += __shfl_xor_sync(0xffffffffu, s,  off);
        ss += __shfl_xor_sync(0xffffffffu, ss, off);
    }
    __shared__ float sh[8];
    int warp = tid >> 5;
    if ((tid & 31) == 0) { sh[warp] = s; sh[4+warp] = ss; }
    __syncthreads();
    s  = sh[0] + sh[1] + sh[2] + sh[3];
    ss = sh[4] + sh[5] + sh[6] + sh[7];
    float mean = s * (1.f/1280.f);
    float var  = ss * (1.f/1280.f) - mean*mean;
    float rstd = rsqrtf(var + 1e-5f);
#pragma unroll
    for (int i = 0; i < 10; i++) {
        int c = tid + i*128;
        yr[c] = (v[i] - mean) * rstd * w[c] + b[c];
    }
}

// ---------------------------------------------------------------------------
// tf32 GEMM: C[M,N] = A[M,K] @ B[K,N] (+bias[N]) (+res[M,N])
// 128x128x16 tiles, 8 warps (4m x 2n), warp tile 32x64, m16n8k8 tf32 mma
// Requirements: K % 16 == 0, N % 128 == 0 (M may be ragged)
// ---------------------------------------------------------------------------
__device__ __forceinline__ uint32_t f2tf(float f) {
    uint32_t u;
    asm("cvt.rna.tf32.f32 %0, %1;" : "=r"(u) : "f"(f));
    return u;
}

__global__ __launch_bounds__(256)
void gemm_tf32(const float* __restrict__ A, const float* __restrict__ B,
               float* C, const float* __restrict__ bias, const float* res,
               int M, int N, int K)
{
    __shared__ uint32_t As[2][128][20];   // pad 16->20: conflict-free frag loads
    __shared__ uint32_t Bs[2][16][136];   // pad 128->136

    int num_m = (M + 127) >> 7;
    int num_n = N >> 7;
    const int GM = 8;                      // threadblock swizzle for L2 reuse
    int pid   = blockIdx.x;
    int npg   = GM * num_n;
    int group = pid / npg;
    int first_m = group * GM;
    int gsz   = min(num_m - first_m, GM);
    int rem   = pid - group * npg;
    int tm    = first_m + (rem % gsz);
    int tn    = rem / gsz;
    int m0 = tm << 7, n0 = tn << 7;

    int tid  = threadIdx.x;
    int warp = tid >> 5, lane = tid & 31;
    int wm = warp & 3, wn = warp >> 2;
    int g  = lane >> 2, t4 = lane & 3;

    float acc[2][8][4];
#pragma unroll
    for (int mi = 0; mi < 2; mi++)
#pragma unroll
        for (int ni = 0; ni < 8; ni++)
#pragma unroll
            for (int i = 0; i < 4; i++) acc[mi][ni][i] = 0.f;

    // gmem load mapping
    int arow = tid >> 1;                   // 0..127
    int acol = (tid & 1) * 8;              // 0 or 8
    int brow = tid >> 5;                   // 0..7 (and +8)
    int bcol = (tid & 31) * 4;

    bool avalid = (m0 + arow) < M;
    const float* aptr = A + (size_t)(m0 + arow) * K + acol;
    const float* bptr = B + (size_t)brow * N + n0 + bcol;

    float4 ra0, ra1, rb0, rb1;
    float4 z4 = make_float4(0.f, 0.f, 0.f, 0.f);

#define LOADG(kt)                                                            \
    do {                                                                     \
        if (avalid) {                                                        \
            const float* _p = aptr + (kt) * 16;                              \
            ra0 = *(const float4*)_p; ra1 = *(const float4*)(_p + 4);        \
        } else { ra0 = z4; ra1 = z4; }                                       \
        const float* _q = bptr + (size_t)(kt) * 16 * N;                      \
        rb0 = *(const float4*)_q;                                            \
        rb1 = *(const float4*)(_q + 8 * (size_t)N);                          \
    } while (0)

#define STORES(nb)                                                           \
    do {                                                                     \
        As[nb][arow][acol+0] = f2tf(ra0.x); As[nb][arow][acol+1] = f2tf(ra0.y); \
        As[nb][arow][acol+2] = f2tf(ra0.z); As[nb][arow][acol+3] = f2tf(ra0.w); \
        As[nb][arow][acol+4] = f2tf(ra1.x); As[nb][arow][acol+5] = f2tf(ra1.y); \
        As[nb][arow][acol+6] = f2tf(ra1.z); As[nb][arow][acol+7] = f2tf(ra1.w); \
        Bs[nb][brow][bcol+0] = f2tf(rb0.x); Bs[nb][brow][bcol+1] = f2tf(rb0.y); \
        Bs[nb][brow][bcol+2] = f2tf(rb0.z); Bs[nb][brow][bcol+3] = f2tf(rb0.w); \
        Bs[nb][brow+8][bcol+0] = f2tf(rb1.x); Bs[nb][brow+8][bcol+1] = f2tf(rb1.y); \
        Bs[nb][brow+8][bcol+2] = f2tf(rb1.z); Bs[nb][brow+8][bcol+3] = f2tf(rb1.w); \
    } while (0)

    int KT = K >> 4;
    LOADG(0);
    STORES(0);
    __syncthreads();

    for (int kt = 0; kt < KT; kt++) {
        int buf = kt & 1;
        bool hasnext = (kt + 1 < KT);
        if (hasnext) LOADG(kt + 1);

#pragma unroll
        for (int ks = 0; ks < 2; ks++) {
            int kk = ks * 8;
            uint32_t af[2][4];
#pragma unroll
            for (int mi = 0; mi < 2; mi++) {
                int rr = wm*32 + mi*16 + g;
                af[mi][0] = As[buf][rr  ][kk + t4];
                af[mi][1] = As[buf][rr+8][kk + t4];
                af[mi][2] = As[buf][rr  ][kk + t4 + 4];
                af[mi][3] = As[buf][rr+8][kk + t4 + 4];
            }
            uint32_t bfr[8][2];
#pragma unroll
            for (int ni = 0; ni < 8; ni++) {
                int cc = wn*64 + ni*8 + g;
                bfr[ni][0] = Bs[buf][kk + t4    ][cc];
                bfr[ni][1] = Bs[buf][kk + t4 + 4][cc];
            }
#pragma unroll
            for (int mi = 0; mi < 2; mi++)
#pragma unroll
                for (int ni = 0; ni < 8; ni++)
                    asm volatile(
                        "mma.sync.aligned.m16n8k8.row.col.f32.tf32.tf32.f32 "
                        "{%0,%1,%2,%3}, {%4,%5,%6,%7}, {%8,%9}, {%0,%1,%2,%3};"
                        : "+f"(acc[mi][ni][0]), "+f"(acc[mi][ni][1]),
                          "+f"(acc[mi][ni][2]), "+f"(acc[mi][ni][3])
                        : "r"(af[mi][0]), "r"(af[mi][1]),
                          "r"(af[mi][2]), "r"(af[mi][3]),
                          "r"(bfr[ni][0]), "r"(bfr[ni][1]));
        }

        if (hasnext) {
            STORES(buf ^ 1);
            __syncthreads();
        }
    }

    // epilogue: + bias + residual
#pragma unroll
    for (int mi = 0; mi < 2; mi++) {
#pragma unroll
        for (int ni = 0; ni < 8; ni++) {
            int row = m0 + wm*32 + mi*16 + g;
            int col = n0 + wn*64 + ni*8 + t4*2;
            float b0 = bias ? bias[col]   : 0.f;
            float b1 = bias ? bias[col+1] : 0.f;
            if (row < M) {
                size_t idx = (size_t)row * N + col;
                float r0 = res ? res[idx]   : 0.f;
                float r1 = res ? res[idx+1] : 0.f;
                C[idx]   = acc[mi][ni][0] + b0 + r0;
                C[idx+1] = acc[mi][ni][1] + b1 + r1;
            }
            if (row + 8 < M) {
                size_t idx = (size_t)(row+8) * N + col;
                float r0 = res ? res[idx]   : 0.f;
                float r1 = res ? res[idx+1] : 0.f;
                C[idx]   = acc[mi][ni][2] + b0 + r0;
                C[idx+1] = acc[mi][ni][3] + b1 + r1;
            }
        }
    }
#undef LOADG
#undef STORES
}

// ---------------------------------------------------------------------------
// Fused attention (fp32, online softmax).
// grid: (ceil(Sq/64), HEADS, n_batch). 256 threads.
// Thread t: q-row r=t/4, dim slice d0=(t%4)*40 of DH=160.
// K/V tiles of 32 rows in smem. sparse=1 -> sparse-causal gather over g_k/g_v
// laid out [32, 256, 1280] (frame0 + former-frame, 512 logical KV rows).
// ---------------------------------------------------------------------------
__global__ __launch_bounds__(256)
void attn_kernel(const float* __restrict__ Q, const float* __restrict__ K,
                 const float* __restrict__ V, float* __restrict__ O,
                 int Sq, int Sk, long kv_bstride, long q_bstride,
                 int sparse, float scale)
{
    __shared__ float Ks[32][160];
    __shared__ float Vs[32][160];

    int batch = blockIdx.z, head = blockIdx.y;
    int q0  = blockIdx.x * 64;
    int tid = threadIdx.x;
    int r   = tid >> 2, c4 = tid & 3;
    int d0  = c4 * 40;
    bool rowvalid = (q0 + r) < Sq;

    float qv[40];
    {
        int rr = rowvalid ? r : 0;
        const float* qp = Q + (size_t)batch * q_bstride
                            + (size_t)(q0 + rr) * DIMC + head * DH + d0;
#pragma unroll
        for (int i = 0; i < 40; i++) qv[i] = rowvalid ? qp[i] : 0.f;
    }

    float o[40];
#pragma unroll
    for (int i = 0; i < 40; i++) o[i] = 0.f;
    float m = -1e30f, l = 0.f;

    int lr = tid >> 3;            // load row 0..31 (8 threads per row)
    int lc = (tid & 7) * 20;      // 20 contiguous floats each

    int ntiles = (Sk + 31) >> 5;
    for (int kt = 0; kt < ntiles; kt++) {
        int j = kt * 32 + lr;
        {
            const float* kp = nullptr;
            const float* vp = nullptr;
            if (j < Sk) {
                size_t off;
                if (sparse) {
                    int bb = batch >> 4, f = batch & 15;
                    int srcf = (j < 256) ? 0 : ((f > 0) ? (f - 1) : 0);
                    int jr2  = (j < 256) ? j : (j - 256);
                    off = ((size_t)(bb*16 + srcf) * 256 + jr2) * DIMC
                        + head * DH + lc;
                } else {
                    off = (size_t)batch * kv_bstride + (size_t)j * DIMC
                        + head * DH + lc;
                }
                kp = K + off; vp = V + off;
            }
#pragma unroll
            for (int i = 0; i < 5; i++) {
                float4 kx = kp ? *(const float4*)(kp + i*4)
                               : make_float4(0,0,0,0);
                float4 vx = vp ? *(const float4*)(vp + i*4)
                               : make_float4(0,0,0,0);
                *(float4*)&Ks[lr][lc + i*4] = kx;
                *(float4*)&Vs[lr][lc + i*4] = vx;
            }
        }
        __syncthreads();

#pragma unroll
        for (int jc = 0; jc < 2; jc++) {
            int jb = jc * 16;
            if (kt*32 + jb < Sk) {
                float p[16];
#pragma unroll
                for (int jj = 0; jj < 16; jj++) {
                    const float4* kr = (const float4*)&Ks[jb + jj][d0];
                    float s0 = 0.f, s1 = 0.f, s2 = 0.f, s3 = 0.f;
#pragma unroll
                    for (int i = 0; i < 10; i++) {
                        float4 k4 = kr[i];
                        s0 += qv[i*4+0]*k4.x; s1 += qv[i*4+1]*k4.y;
                        s2 += qv[i*4+2]*k4.z; s3 += qv[i*4+3]*k4.w;
                    }
                    p[jj] = (s0 + s1) + (s2 + s3);
                }
#pragma unroll
                for (int jj = 0; jj < 16; jj++) {
                    p[jj] += __shfl_xor_sync(0xffffffffu, p[jj], 1);
                    p[jj] += __shfl_xor_sync(0xffffffffu, p[jj], 2);
                    int jg = kt*32 + jb + jj;
                    p[jj] = (jg < Sk) ? p[jj] * scale : -1e30f;
                }
                float mt = m;
#pragma unroll
                for (int jj = 0; jj < 16; jj++) mt = fmaxf(mt, p[jj]);
                if (mt > m) {
                    float sc = __expf(m - mt);
                    l *= sc;
#pragma unroll
                    for (int i = 0; i < 40; i++) o[i] *= sc;
                    m = mt;
                }
#pragma unroll
                for (int jj = 0; jj < 16; jj++) {
                    float e = __expf(p[jj] - m);
                    l += e;
                    const float4* vr = (const float4*)&Vs[jb + jj][d0];
#pragma unroll
                    for (int i = 0; i < 10; i++) {
                        float4 v4 = vr[i];
                        o[i*4+0] += e * v4.x; o[i*4+1] += e * v4.y;
                        o[i*4+2] += e * v4.z; o[i*4+3] += e * v4.w;
                    }
                }
            }
        }
        __syncthreads();
    }

    if (rowvalid) {
        float inv = 1.f / l;
        float* op = O + (size_t)batch * q_bstride
                      + (size_t)(q0 + r) * DIMC + head * DH + d0;
#pragma unroll
        for (int i = 0; i < 40; i++) op[i] = o[i] * inv;
    }
}

// ---------------------------------------------------------------------------
// GEGLU: out[r][i] = p * gelu_exact(g), p = in[r][i], g = in[r][5120+i]
// ---------------------------------------------------------------------------
__global__ void geglu_kernel(const float* __restrict__ in, float* __restrict__ out)
{
    size_t idx = (size_t)blockIdx.x * blockDim.x + threadIdx.x;
    if (idx >= (size_t)NROWS * FF_I) return;
    size_t rr = idx / FF_I;
    int    i  = (int)(idx - rr * FF_I);
    const float* row = in + rr * FF_N;
    float p = row[i];
    float g = row[FF_I + i];
    float gel = 0.5f * g * (1.f + erff(g * 0.70710678118654752f));
    out[idx] = p * gel;
}

// ---------------------------------------------------------------------------
// Temporal reshape transposes
// fwd: ht[(b*256+tok)*16+f][c] = h[(b*16+f)*256+tok][c]
// ---------------------------------------------------------------------------
__global__ void transpose_fwd(const float* __restrict__ in, float* __restrict__ out)
{
    size_t idx = (size_t)blockIdx.x * blockDim.x + threadIdx.x;
    if (idx >= (size_t)NROWS * DIMC) return;
    int c   = (int)(idx % DIMC);
    int row = (int)(idx / DIMC);            // out row = b*4096 + tok*16 + f
    int f   = row & 15;
    int tok = (row >> 4) & 255;
    int b   = row >> 12;
    out[idx] = in[((size_t)((b*16 + f)*256 + tok)) * DIMC + c];
}

__global__ void transpose_bwd(const float* __restrict__ in, float* __restrict__ out)
{
    size_t idx = (size_t)blockIdx.x * blockDim.x + threadIdx.x;
    if (idx >= (size_t)NROWS * DIMC) return;
    int c   = (int)(idx % DIMC);
    int row = (int)(idx / DIMC);            // out row = b*4096 + f*256 + tok
    int tok = row & 255;
    int f   = (row >> 8) & 15;
    int b   = row >> 12;
    out[idx] = in[((size_t)((b*256 + tok)*16 + f)) * DIMC + c];
}

// ---------------------------------------------------------------------------
// Host launcher
// ---------------------------------------------------------------------------
static void launch_gemm(const float* A, const float* B, float* C,
                        const float* bias, const float* res,
                        int M, int N, int K)
{
    int num_m = (M + 127) / 128, num_n = N / 128;
    gemm_tf32<<<num_m * num_n, 256>>>(A, B, C, bias, res, M, N, K);
}

extern "C" void kernel_launch(void* const* d_in, const int* in_sizes, int n_in,
                              void* d_out, int out_size)
{
    const float* hid  = (const float*)d_in[0];
    const float* enc  = (const float*)d_in[1];
    const float* n1w  = (const float*)d_in[2];
    const float* n1b  = (const float*)d_in[3];
    const float* a1wq = (const float*)d_in[4];
    const float* a1wk = (const float*)d_in[5];
    const float* a1wv = (const float*)d_in[6];
    const float* a1wo = (const float*)d_in[7];
    const float* a1bo = (const float*)d_in[8];
    const float* n2w  = (const float*)d_in[9];
    const float* n2b  = (const float*)d_in[10];
    const float* a2wq = (const float*)d_in[11];
    const float* a2wk = (const float*)d_in[12];
    const float* a2wv = (const float*)d_in[13];
    const float* a2wo = (const float*)d_in[14];
    const float* a2bo = (const float*)d_in[15];
    const float* n3w  = (const float*)d_in[16];
    const float* n3b  = (const float*)d_in[17];
    const float* ffw1 = (const float*)d_in[18];
    const float* ffb1 = (const float*)d_in[19];
    const float* ffw2 = (const float*)d_in[20];
    const float* ffb2 = (const float*)d_in[21];
    const float* ntw  = (const float*)d_in[22];
    const float* ntb  = (const float*)d_in[23];
    const float* atwq = (const float*)d_in[24];
    const float* atwk = (const float*)d_in[25];
    const float* atwv = (const float*)d_in[26];
    const float* atwo = (const float*)d_in[27];
    const float* atbo = (const float*)d_in[28];
    // d_in[29] = video_length (16, compile-time constant here)

    float* out = (float*)d_out;

    float *nh, *q, *k, *v, *ao, *ht, *ff1, *gg, *enck, *encv;
    cudaGetSymbolAddress((void**)&nh,  g_nh);
    cudaGetSymbolAddress((void**)&q,   g_q);
    cudaGetSymbolAddress((void**)&k,   g_k);
    cudaGetSymbolAddress((void**)&v,   g_v);
    cudaGetSymbolAddress((void**)&ao,  g_ao);
    cudaGetSymbolAddress((void**)&ht,  g_ht);
    cudaGetSymbolAddress((void**)&ff1, g_ff1);
    cudaGetSymbolAddress((void**)&gg,  g_gg);
    cudaGetSymbolAddress((void**)&enck,g_enck);
    cudaGetSymbolAddress((void**)&encv,g_encv);

    const float scale = 0.07905694150420949f;   // 160^-0.5
    const long QBS = (long)TOK * DIMC;          // 327680

    // ---- attn1: sparse-causal self-attention ----
    ln_kernel<<<NROWS, 128>>>(hid, n1w, n1b, nh);
    launch_gemm(nh, a1wq, q, nullptr, nullptr, NROWS, DIMC, DIMC);
    launch_gemm(nh, a1wk, k, nullptr, nullptr, NROWS, DIMC, DIMC);
    launch_gemm(nh, a1wv, v, nullptr, nullptr, NROWS, DIMC, DIMC);
    attn_kernel<<<dim3(4, HEADS, BF), 256>>>(q, k, v, ao,
        TOK, 2*TOK, QBS, QBS, 1, scale);
    launch_gemm(ao, a1wo, out, a1bo, hid, NROWS, DIMC, DIMC);

    // ---- attn2: cross-attention ----
    ln_kernel<<<NROWS, 128>>>(out, n2w, n2b, nh);
    launch_gemm(nh,  a2wq, q,    nullptr, nullptr, NROWS,   DIMC, DIMC);
    launch_gemm(enc, a2wk, enck, nullptr, nullptr, ENCROWS, DIMC, CROSS);
    launch_gemm(enc, a2wv, encv, nullptr, nullptr, ENCROWS, DIMC, CROSS);
    attn_kernel<<<dim3(4, HEADS, BF), 256>>>(q, enck, encv, ao,
        TOK, ESEQ, (long)ESEQ * DIMC, QBS, 0, scale);
    launch_gemm(ao, a2wo, out, a2bo, out, NROWS, DIMC, DIMC);

    // ---- geglu FFN ----
    ln_kernel<<<NROWS, 128>>>(out, n3w, n3b, nh);
    launch_gemm(nh, ffw1, ff1, ffb1, nullptr, NROWS, FF_N, DIMC);
    {
        size_t tot = (size_t)NROWS * FF_I;
        geglu_kernel<<<(unsigned)((tot + 255) / 256), 256>>>(ff1, gg);
    }
    launch_gemm(gg, ffw2, out, ffb2, out, NROWS, DIMC, FF_I);

    // ---- temporal self-attention ----
    {
        size_t tot = (size_t)NROWS * DIMC;
        transpose_fwd<<<(unsigned)((tot + 255) / 256), 256>>>(out, ht);
    }
    ln_kernel<<<NROWS, 128>>>(ht, ntw, ntb, nh);
    launch_gemm(nh, atwq, q, nullptr, nullptr, NROWS, DIMC, DIMC);
    launch_gemm(nh, atwk, k, nullptr, nullptr, NROWS, DIMC, DIMC);
    launch_gemm(nh, atwv, v, nullptr, nullptr, NROWS, DIMC, DIMC);
    // temporal: 512 sequences (= B * TOK), each FRAMES long  [BUGFIX: was BF*TOK]
    attn_kernel<<<dim3(1, HEADS, 2*TOK), 256>>>(q, k, v, ao,
        FRAMES, FRAMES, (long)FRAMES * DIMC, (long)FRAMES * DIMC, 0, scale);
    launch_gemm(ao, atwo, ht, atbo, ht, NROWS, DIMC, DIMC);
    {
        size_t tot = (size_t)NROWS * DIMC;
        transpose_bwd<<<(unsigned)((tot + 255) / 256), 256>>>(ht, out);
    }
}